// round 2
// baseline (speedup 1.0000x reference)
#include <cuda_runtime.h>
#include <math.h>

#define BB 16
#define CC 3
#define HH 384
#define WW 1280
#define HW (HH * WW)
#define EPSF 1e-7f
#define PX 4   // pixels per thread (horizontal, float4-aligned)

// Per-batch fused transform: coord = d * A @ [x,y,1] + tv   (A = K R K^-1, tv = K t)
__device__ float g_A[BB][9];
__device__ float g_tv[BB][3];

__global__ void precompute_mats(const float* __restrict__ pose,
                                const float* __restrict__ intr) {
    int b = threadIdx.x;
    if (b >= BB) return;

    float K[9];
#pragma unroll
    for (int i = 0; i < 9; i++) K[i] = intr[b * 9 + i];

    // inverse via adjugate
    float c00 =  (K[4] * K[8] - K[5] * K[7]);
    float c01 = -(K[3] * K[8] - K[5] * K[6]);
    float c02 =  (K[3] * K[7] - K[4] * K[6]);
    float det = K[0] * c00 + K[1] * c01 + K[2] * c02;
    float id = 1.0f / det;
    float inv[9];
    inv[0] = c00 * id;
    inv[1] = -(K[1] * K[8] - K[2] * K[7]) * id;
    inv[2] =  (K[1] * K[5] - K[2] * K[4]) * id;
    inv[3] = c01 * id;
    inv[4] =  (K[0] * K[8] - K[2] * K[6]) * id;
    inv[5] = -(K[0] * K[5] - K[2] * K[3]) * id;
    inv[6] = c02 * id;
    inv[7] = -(K[0] * K[7] - K[1] * K[6]) * id;
    inv[8] =  (K[0] * K[4] - K[1] * K[3]) * id;

    // Rodrigues rotation from axis-angle (matches reference: axis = aa/(theta+EPS))
    float ax = pose[b * 6 + 0], ay = pose[b * 6 + 1], az = pose[b * 6 + 2];
    float theta = sqrtf(ax * ax + ay * ay + az * az);
    float ith = 1.0f / (theta + EPSF);
    float x = ax * ith, y = ay * ith, z = az * ith;
    float c = cosf(theta), s = sinf(theta), t = 1.0f - c;
    float R[9];
    R[0] = t * x * x + c;     R[1] = t * x * y - s * z; R[2] = t * z * x + s * y;
    R[3] = t * x * y + s * z; R[4] = t * y * y + c;     R[5] = t * y * z - s * x;
    R[6] = t * z * x - s * y; R[7] = t * y * z + s * x; R[8] = t * z * z + c;

    // A = K * R * invK
    float KR[9];
#pragma unroll
    for (int i = 0; i < 3; i++)
#pragma unroll
        for (int j = 0; j < 3; j++) {
            float sum = 0.0f;
#pragma unroll
            for (int k = 0; k < 3; k++) sum += K[i * 3 + k] * R[k * 3 + j];
            KR[i * 3 + j] = sum;
        }
#pragma unroll
    for (int i = 0; i < 3; i++)
#pragma unroll
        for (int j = 0; j < 3; j++) {
            float sum = 0.0f;
#pragma unroll
            for (int k = 0; k < 3; k++) sum += KR[i * 3 + k] * inv[k * 3 + j];
            g_A[b][i * 3 + j] = sum;
        }

    // tv = K * t
    float tx = pose[b * 6 + 3], ty = pose[b * 6 + 4], tz = pose[b * 6 + 5];
    g_tv[b][0] = K[0] * tx + K[1] * ty + K[2] * tz;
    g_tv[b][1] = K[3] * tx + K[4] * ty + K[5] * tz;
    g_tv[b][2] = K[6] * tx + K[7] * ty + K[8] * tz;
}

__global__ void __launch_bounds__(256)
warp_sample_kernel(const float* __restrict__ img,
                   const float* __restrict__ depth,
                   float* __restrict__ out) {
    int tid = blockIdx.x * blockDim.x + threadIdx.x;
    int pix0 = tid * PX;
    if (pix0 >= BB * HW) return;

    int b = pix0 / HW;
    int rem = pix0 - b * HW;          // rem % 4 == 0, same row for all PX pixels
    int h = rem / WW;
    int w = rem - h * WW;

    // per-batch coefficients (broadcast within block)
    float a0 = g_A[b][0], a1 = g_A[b][1], a2 = g_A[b][2];
    float a3 = g_A[b][3], a4 = g_A[b][4], a5 = g_A[b][5];
    float a6 = g_A[b][6], a7 = g_A[b][7], a8 = g_A[b][8];
    float t0 = g_tv[b][0], t1 = g_tv[b][1], t2 = g_tv[b][2];

    float4 d4 = *reinterpret_cast<const float4*>(depth + pix0);
    float dv[PX] = {d4.x, d4.y, d4.z, d4.w};

    float fy = (float)h;
    // row-direction partials (independent of w)
    float rx = a1 * fy + a2;
    float ry = a4 * fy + a5;
    float rz = a7 * fy + a8;

    int   i00[PX], i10[PX], i01[PX], i11[PX];
    float w00[PX], w10[PX], w01[PX], w11[PX];

#pragma unroll
    for (int p = 0; p < PX; p++) {
        float fx = (float)(w + p);
        float d  = dv[p];
        float X = d * (a0 * fx + rx) + t0;
        float Y = d * (a3 * fx + ry) + t1;
        float Z = d * (a6 * fx + rz) + t2 + EPSF;

        float xs = __fdividef(X, Z);
        float ys = __fdividef(Y, Z);

        float x0f = floorf(xs), y0f = floorf(ys);
        float x1f = x0f + 1.0f, y1f = y0f + 1.0f;
        float wx1 = xs - x0f, wx0 = 1.0f - wx1;
        float wy1 = ys - y0f, wy0 = 1.0f - wy1;

        // in-bounds masks on the UNCLIPPED coordinates (reference semantics)
        float ib_x0 = (x0f >= 0.0f && x0f <= (float)(WW - 1)) ? 1.0f : 0.0f;
        float ib_x1 = (x1f >= 0.0f && x1f <= (float)(WW - 1)) ? 1.0f : 0.0f;
        float ib_y0 = (y0f >= 0.0f && y0f <= (float)(HH - 1)) ? 1.0f : 0.0f;
        float ib_y1 = (y1f >= 0.0f && y1f <= (float)(HH - 1)) ? 1.0f : 0.0f;

        // clamp, then gather
        int xc0 = (int)fminf(fmaxf(x0f, 0.0f), (float)(WW - 1));
        int xc1 = (int)fminf(fmaxf(x1f, 0.0f), (float)(WW - 1));
        int yc0 = (int)fminf(fmaxf(y0f, 0.0f), (float)(HH - 1));
        int yc1 = (int)fminf(fmaxf(y1f, 0.0f), (float)(HH - 1));

        w00[p] = wx0 * wy0 * ib_x0 * ib_y0;
        w10[p] = wx1 * wy0 * ib_x1 * ib_y0;
        w01[p] = wx0 * wy1 * ib_x0 * ib_y1;
        w11[p] = wx1 * wy1 * ib_x1 * ib_y1;

        int r0 = yc0 * WW;
        int r1 = yc1 * WW;
        i00[p] = r0 + xc0;
        i10[p] = r0 + xc1;
        i01[p] = r1 + xc0;
        i11[p] = r1 + xc1;
    }

    int base = b * CC * HW;
#pragma unroll
    for (int c = 0; c < CC; c++) {
        const float* plane = img + base + c * HW;
        float v[PX];
#pragma unroll
        for (int p = 0; p < PX; p++) {
            v[p] = w00[p] * __ldg(plane + i00[p]) +
                   w10[p] * __ldg(plane + i10[p]) +
                   w01[p] * __ldg(plane + i01[p]) +
                   w11[p] * __ldg(plane + i11[p]);
        }
        float4 o4 = make_float4(v[0], v[1], v[2], v[3]);
        *reinterpret_cast<float4*>(out + base + c * HW + rem) = o4;
    }
}

extern "C" void kernel_launch(void* const* d_in, const int* in_sizes, int n_in,
                              void* d_out, int out_size) {
    const float* source_image = (const float*)d_in[0];
    const float* depth_map    = (const float*)d_in[1];
    const float* pose         = (const float*)d_in[2];
    const float* intrinsic    = (const float*)d_in[3];
    float* out = (float*)d_out;

    precompute_mats<<<1, 32>>>(pose, intrinsic);

    const int total_threads = BB * HW / PX;
    const int threads = 256;
    const int blocks = (total_threads + threads - 1) / threads;
    warp_sample_kernel<<<blocks, threads>>>(source_image, depth_map, out);
}

// round 3
// speedup vs baseline: 1.2586x; 1.2586x over previous
#include <cuda_runtime.h>
#include <math.h>

#define BB 16
#define CC 3
#define HH 384
#define WW 1280
#define HW (HH * WW)
#define EPSF 1e-7f

// Per-batch fused transform: coord = d * A @ [x,y,1] + tv   (A = K R K^-1, tv = K t)
__device__ float g_A[BB][9];
__device__ float g_tv[BB][3];

__global__ void precompute_mats(const float* __restrict__ pose,
                                const float* __restrict__ intr) {
    int b = threadIdx.x;
    if (b >= BB) return;

    float K[9];
#pragma unroll
    for (int i = 0; i < 9; i++) K[i] = intr[b * 9 + i];

    float c00 =  (K[4] * K[8] - K[5] * K[7]);
    float c01 = -(K[3] * K[8] - K[5] * K[6]);
    float c02 =  (K[3] * K[7] - K[4] * K[6]);
    float det = K[0] * c00 + K[1] * c01 + K[2] * c02;
    float id = 1.0f / det;
    float inv[9];
    inv[0] = c00 * id;
    inv[1] = -(K[1] * K[8] - K[2] * K[7]) * id;
    inv[2] =  (K[1] * K[5] - K[2] * K[4]) * id;
    inv[3] = c01 * id;
    inv[4] =  (K[0] * K[8] - K[2] * K[6]) * id;
    inv[5] = -(K[0] * K[5] - K[2] * K[3]) * id;
    inv[6] = c02 * id;
    inv[7] = -(K[0] * K[7] - K[1] * K[6]) * id;
    inv[8] =  (K[0] * K[4] - K[1] * K[3]) * id;

    float ax = pose[b * 6 + 0], ay = pose[b * 6 + 1], az = pose[b * 6 + 2];
    float theta = sqrtf(ax * ax + ay * ay + az * az);
    float ith = 1.0f / (theta + EPSF);
    float x = ax * ith, y = ay * ith, z = az * ith;
    float c = cosf(theta), s = sinf(theta), t = 1.0f - c;
    float R[9];
    R[0] = t * x * x + c;     R[1] = t * x * y - s * z; R[2] = t * z * x + s * y;
    R[3] = t * x * y + s * z; R[4] = t * y * y + c;     R[5] = t * y * z - s * x;
    R[6] = t * z * x - s * y; R[7] = t * y * z + s * x; R[8] = t * z * z + c;

    float KR[9];
#pragma unroll
    for (int i = 0; i < 3; i++)
#pragma unroll
        for (int j = 0; j < 3; j++) {
            float sum = 0.0f;
#pragma unroll
            for (int k = 0; k < 3; k++) sum += K[i * 3 + k] * R[k * 3 + j];
            KR[i * 3 + j] = sum;
        }
#pragma unroll
    for (int i = 0; i < 3; i++)
#pragma unroll
        for (int j = 0; j < 3; j++) {
            float sum = 0.0f;
#pragma unroll
            for (int k = 0; k < 3; k++) sum += KR[i * 3 + k] * inv[k * 3 + j];
            g_A[b][i * 3 + j] = sum;
        }

    float tx = pose[b * 6 + 3], ty = pose[b * 6 + 4], tz = pose[b * 6 + 5];
    g_tv[b][0] = K[0] * tx + K[1] * ty + K[2] * tz;
    g_tv[b][1] = K[3] * tx + K[4] * ty + K[5] * tz;
    g_tv[b][2] = K[6] * tx + K[7] * ty + K[8] * tz;
}

// One thread = 2 horizontally adjacent pixels, fully scalarized.
// __launch_bounds__(256, 4): 64-reg budget -> no spills, 50% occ target.
__global__ void __launch_bounds__(256, 4)
warp_sample_kernel(const float* __restrict__ img,
                   const float* __restrict__ depth,
                   float* __restrict__ out) {
    int tid = blockIdx.x * blockDim.x + threadIdx.x;
    int pix0 = tid * 2;
    if (pix0 >= BB * HW) return;

    int b = pix0 / HW;
    int rem = pix0 - b * HW;          // even; both pixels on the same row
    int h = rem / WW;
    int w = rem - h * WW;

    float a0 = g_A[b][0], a1 = g_A[b][1], a2 = g_A[b][2];
    float a3 = g_A[b][3], a4 = g_A[b][4], a5 = g_A[b][5];
    float a6 = g_A[b][6], a7 = g_A[b][7], a8 = g_A[b][8];
    float t0 = g_tv[b][0], t1 = g_tv[b][1], t2 = g_tv[b][2];

    float2 d2 = __ldcs(reinterpret_cast<const float2*>(depth + pix0));

    float fy = (float)h;
    float rx = a1 * fy + a2;
    float ry = a4 * fy + a5;
    float rz = a7 * fy + a8;

    // ---- pixel A ----
    float fxA = (float)w;
    float XA = d2.x * (a0 * fxA + rx) + t0;
    float YA = d2.x * (a3 * fxA + ry) + t1;
    float ZA = d2.x * (a6 * fxA + rz) + t2 + EPSF;
    float xsA = __fdividef(XA, ZA);
    float ysA = __fdividef(YA, ZA);

    float x0fA = floorf(xsA), y0fA = floorf(ysA);
    float wx1A = xsA - x0fA, wx0A = 1.0f - wx1A;
    float wy1A = ysA - y0fA, wy0A = 1.0f - wy1A;
    float x1fA = x0fA + 1.0f, y1fA = y0fA + 1.0f;

    float ibx0A = (x0fA >= 0.0f && x0fA <= (float)(WW - 1)) ? 1.0f : 0.0f;
    float ibx1A = (x1fA >= 0.0f && x1fA <= (float)(WW - 1)) ? 1.0f : 0.0f;
    float iby0A = (y0fA >= 0.0f && y0fA <= (float)(HH - 1)) ? 1.0f : 0.0f;
    float iby1A = (y1fA >= 0.0f && y1fA <= (float)(HH - 1)) ? 1.0f : 0.0f;

    int xc0A = (int)fminf(fmaxf(x0fA, 0.0f), (float)(WW - 1));
    int xc1A = (int)fminf(fmaxf(x1fA, 0.0f), (float)(WW - 1));
    int yc0A = (int)fminf(fmaxf(y0fA, 0.0f), (float)(HH - 1));
    int yc1A = (int)fminf(fmaxf(y1fA, 0.0f), (float)(HH - 1));

    float w00A = wx0A * wy0A * ibx0A * iby0A;
    float w10A = wx1A * wy0A * ibx1A * iby0A;
    float w01A = wx0A * wy1A * ibx0A * iby1A;
    float w11A = wx1A * wy1A * ibx1A * iby1A;

    int i00A = yc0A * WW + xc0A;
    int i10A = yc0A * WW + xc1A;
    int i01A = yc1A * WW + xc0A;
    int i11A = yc1A * WW + xc1A;

    // ---- pixel B ----
    float fxB = (float)(w + 1);
    float XB = d2.y * (a0 * fxB + rx) + t0;
    float YB = d2.y * (a3 * fxB + ry) + t1;
    float ZB = d2.y * (a6 * fxB + rz) + t2 + EPSF;
    float xsB = __fdividef(XB, ZB);
    float ysB = __fdividef(YB, ZB);

    float x0fB = floorf(xsB), y0fB = floorf(ysB);
    float wx1B = xsB - x0fB, wx0B = 1.0f - wx1B;
    float wy1B = ysB - y0fB, wy0B = 1.0f - wy1B;
    float x1fB = x0fB + 1.0f, y1fB = y0fB + 1.0f;

    float ibx0B = (x0fB >= 0.0f && x0fB <= (float)(WW - 1)) ? 1.0f : 0.0f;
    float ibx1B = (x1fB >= 0.0f && x1fB <= (float)(WW - 1)) ? 1.0f : 0.0f;
    float iby0B = (y0fB >= 0.0f && y0fB <= (float)(HH - 1)) ? 1.0f : 0.0f;
    float iby1B = (y1fB >= 0.0f && y1fB <= (float)(HH - 1)) ? 1.0f : 0.0f;

    int xc0B = (int)fminf(fmaxf(x0fB, 0.0f), (float)(WW - 1));
    int xc1B = (int)fminf(fmaxf(x1fB, 0.0f), (float)(WW - 1));
    int yc0B = (int)fminf(fmaxf(y0fB, 0.0f), (float)(HH - 1));
    int yc1B = (int)fminf(fmaxf(y1fB, 0.0f), (float)(HH - 1));

    float w00B = wx0B * wy0B * ibx0B * iby0B;
    float w10B = wx1B * wy0B * ibx1B * iby0B;
    float w01B = wx0B * wy1B * ibx0B * iby1B;
    float w11B = wx1B * wy1B * ibx1B * iby1B;

    int i00B = yc0B * WW + xc0B;
    int i10B = yc0B * WW + xc1B;
    int i01B = yc1B * WW + xc0B;
    int i11B = yc1B * WW + xc1B;

    int base = b * CC * HW;
#pragma unroll
    for (int c = 0; c < CC; c++) {
        const float* plane = img + base + c * HW;
        float vA = w00A * __ldg(plane + i00A) + w10A * __ldg(plane + i10A) +
                   w01A * __ldg(plane + i01A) + w11A * __ldg(plane + i11A);
        float vB = w00B * __ldg(plane + i00B) + w10B * __ldg(plane + i10B) +
                   w01B * __ldg(plane + i01B) + w11B * __ldg(plane + i11B);
        __stcs(reinterpret_cast<float2*>(out + base + c * HW + rem),
               make_float2(vA, vB));
    }
}

extern "C" void kernel_launch(void* const* d_in, const int* in_sizes, int n_in,
                              void* d_out, int out_size) {
    const float* source_image = (const float*)d_in[0];
    const float* depth_map    = (const float*)d_in[1];
    const float* pose         = (const float*)d_in[2];
    const float* intrinsic    = (const float*)d_in[3];
    float* out = (float*)d_out;

    precompute_mats<<<1, 32>>>(pose, intrinsic);

    const int total_threads = BB * HW / 2;
    const int threads = 256;
    const int blocks = (total_threads + threads - 1) / threads;
    warp_sample_kernel<<<blocks, threads>>>(source_image, depth_map, out);
}

// round 4
// speedup vs baseline: 1.2971x; 1.0306x over previous
#include <cuda_runtime.h>
#include <cuda_fp16.h>
#include <math.h>

#define BB 16
#define CC 3
#define HH 384
#define WW 1280
#define HW (HH * WW)
#define EPSF 1e-7f

// Per-batch fused transform: coord = d * A @ [x,y,1] + tv   (A = K R K^-1, tv = K t)
__device__ float g_A[BB][9];
__device__ float g_tv[BB][3];

// HWC fp16 staging: per pixel 4 halves {R,G,B,pad} = 8 bytes, aligned.
// 16*384*1280*4 halves = 62.9 MB static device scratch (allowed; no runtime alloc).
__device__ __half2 g_hwc[(size_t)BB * HW * 2];

__global__ void precompute_mats(const float* __restrict__ pose,
                                const float* __restrict__ intr) {
    int b = threadIdx.x;
    if (b >= BB) return;

    float K[9];
#pragma unroll
    for (int i = 0; i < 9; i++) K[i] = intr[b * 9 + i];

    float c00 =  (K[4] * K[8] - K[5] * K[7]);
    float c01 = -(K[3] * K[8] - K[5] * K[6]);
    float c02 =  (K[3] * K[7] - K[4] * K[6]);
    float det = K[0] * c00 + K[1] * c01 + K[2] * c02;
    float id = 1.0f / det;
    float inv[9];
    inv[0] = c00 * id;
    inv[1] = -(K[1] * K[8] - K[2] * K[7]) * id;
    inv[2] =  (K[1] * K[5] - K[2] * K[4]) * id;
    inv[3] = c01 * id;
    inv[4] =  (K[0] * K[8] - K[2] * K[6]) * id;
    inv[5] = -(K[0] * K[5] - K[2] * K[3]) * id;
    inv[6] = c02 * id;
    inv[7] = -(K[0] * K[7] - K[1] * K[6]) * id;
    inv[8] =  (K[0] * K[4] - K[1] * K[3]) * id;

    float ax = pose[b * 6 + 0], ay = pose[b * 6 + 1], az = pose[b * 6 + 2];
    float theta = sqrtf(ax * ax + ay * ay + az * az);
    float ith = 1.0f / (theta + EPSF);
    float x = ax * ith, y = ay * ith, z = az * ith;
    float c = cosf(theta), s = sinf(theta), t = 1.0f - c;
    float R[9];
    R[0] = t * x * x + c;     R[1] = t * x * y - s * z; R[2] = t * z * x + s * y;
    R[3] = t * x * y + s * z; R[4] = t * y * y + c;     R[5] = t * y * z - s * x;
    R[6] = t * z * x - s * y; R[7] = t * y * z + s * x; R[8] = t * z * z + c;

    float KR[9];
#pragma unroll
    for (int i = 0; i < 3; i++)
#pragma unroll
        for (int j = 0; j < 3; j++) {
            float sum = 0.0f;
#pragma unroll
            for (int k = 0; k < 3; k++) sum += K[i * 3 + k] * R[k * 3 + j];
            KR[i * 3 + j] = sum;
        }
#pragma unroll
    for (int i = 0; i < 3; i++)
#pragma unroll
        for (int j = 0; j < 3; j++) {
            float sum = 0.0f;
#pragma unroll
            for (int k = 0; k < 3; k++) sum += KR[i * 3 + k] * inv[k * 3 + j];
            g_A[b][i * 3 + j] = sum;
        }

    float tx = pose[b * 6 + 3], ty = pose[b * 6 + 4], tz = pose[b * 6 + 5];
    g_tv[b][0] = K[0] * tx + K[1] * ty + K[2] * tz;
    g_tv[b][1] = K[3] * tx + K[4] * ty + K[5] * tz;
    g_tv[b][2] = K[6] * tx + K[7] * ty + K[8] * tz;
}

// CHW fp32 -> HWC fp16x4 pack. One thread = 2 pixels. Pure streaming.
__global__ void __launch_bounds__(256)
pack_hwc_kernel(const float* __restrict__ img) {
    int tid = blockIdx.x * blockDim.x + threadIdx.x;
    int p = tid * 2;
    if (p >= BB * HW) return;

    int b = p / HW;
    int rem = p - b * HW;
    const float* plane = img + (size_t)b * CC * HW;

    float2 r = __ldcs(reinterpret_cast<const float2*>(plane + rem));
    float2 g = __ldcs(reinterpret_cast<const float2*>(plane + HW + rem));
    float2 bl = __ldcs(reinterpret_cast<const float2*>(plane + 2 * HW + rem));

    __half2 h0 = __floats2half2_rn(r.x, g.x);
    __half2 h1 = __floats2half2_rn(bl.x, 0.0f);
    __half2 h2 = __floats2half2_rn(r.y, g.y);
    __half2 h3 = __floats2half2_rn(bl.y, 0.0f);

    uint4 packed;
    packed.x = *reinterpret_cast<unsigned int*>(&h0);
    packed.y = *reinterpret_cast<unsigned int*>(&h1);
    packed.z = *reinterpret_cast<unsigned int*>(&h2);
    packed.w = *reinterpret_cast<unsigned int*>(&h3);
    *reinterpret_cast<uint4*>(&g_hwc[(size_t)p * 2]) = packed;  // 16B aligned
}

__device__ __forceinline__ void tap_rgb(const uint2* __restrict__ src, int idx,
                                        float wgt, float& vr, float& vg, float& vb) {
    uint2 raw = __ldg(src + idx);
    __half2 rg = *reinterpret_cast<__half2*>(&raw.x);
    __half2 bp = *reinterpret_cast<__half2*>(&raw.y);
    float2 rgf = __half22float2(rg);
    float bf = __low2float(bp);
    vr = fmaf(wgt, rgf.x, vr);
    vg = fmaf(wgt, rgf.y, vg);
    vb = fmaf(wgt, bf, vb);
}

// One thread = 2 horizontally adjacent pixels, HWC fp16 gathers (4 taps/px).
__global__ void __launch_bounds__(256, 4)
warp_sample_kernel(const float* __restrict__ depth,
                   float* __restrict__ out) {
    int tid = blockIdx.x * blockDim.x + threadIdx.x;
    int pix0 = tid * 2;
    if (pix0 >= BB * HW) return;

    int b = pix0 / HW;
    int rem = pix0 - b * HW;          // even; both pixels on the same row
    int h = rem / WW;
    int w = rem - h * WW;

    float a0 = g_A[b][0], a1 = g_A[b][1], a2 = g_A[b][2];
    float a3 = g_A[b][3], a4 = g_A[b][4], a5 = g_A[b][5];
    float a6 = g_A[b][6], a7 = g_A[b][7], a8 = g_A[b][8];
    float t0 = g_tv[b][0], t1 = g_tv[b][1], t2 = g_tv[b][2];

    float2 d2 = __ldcs(reinterpret_cast<const float2*>(depth + pix0));

    float fy = (float)h;
    float rx = a1 * fy + a2;
    float ry = a4 * fy + a5;
    float rz = a7 * fy + a8;

    const uint2* src = reinterpret_cast<const uint2*>(g_hwc) + (size_t)b * HW;

    float vrA = 0.0f, vgA = 0.0f, vbA = 0.0f;
    float vrB = 0.0f, vgB = 0.0f, vbB = 0.0f;

#pragma unroll
    for (int p = 0; p < 2; p++) {
        float fx = (float)(w + p);
        float d  = (p == 0) ? d2.x : d2.y;
        float X = d * (a0 * fx + rx) + t0;
        float Y = d * (a3 * fx + ry) + t1;
        float Z = d * (a6 * fx + rz) + t2 + EPSF;

        float xs = __fdividef(X, Z);
        float ys = __fdividef(Y, Z);

        float x0f = floorf(xs), y0f = floorf(ys);
        float x1f = x0f + 1.0f, y1f = y0f + 1.0f;
        float wx1 = xs - x0f, wx0 = 1.0f - wx1;
        float wy1 = ys - y0f, wy0 = 1.0f - wy1;

        // in-bounds masks on UNCLIPPED coords (reference semantics)
        float ibx0 = (x0f >= 0.0f && x0f <= (float)(WW - 1)) ? 1.0f : 0.0f;
        float ibx1 = (x1f >= 0.0f && x1f <= (float)(WW - 1)) ? 1.0f : 0.0f;
        float iby0 = (y0f >= 0.0f && y0f <= (float)(HH - 1)) ? 1.0f : 0.0f;
        float iby1 = (y1f >= 0.0f && y1f <= (float)(HH - 1)) ? 1.0f : 0.0f;

        int xc0 = (int)fminf(fmaxf(x0f, 0.0f), (float)(WW - 1));
        int xc1 = (int)fminf(fmaxf(x1f, 0.0f), (float)(WW - 1));
        int yc0 = (int)fminf(fmaxf(y0f, 0.0f), (float)(HH - 1));
        int yc1 = (int)fminf(fmaxf(y1f, 0.0f), (float)(HH - 1));

        float w00 = wx0 * wy0 * ibx0 * iby0;
        float w10 = wx1 * wy0 * ibx1 * iby0;
        float w01 = wx0 * wy1 * ibx0 * iby1;
        float w11 = wx1 * wy1 * ibx1 * iby1;

        int r0 = yc0 * WW;
        int r1 = yc1 * WW;

        float vr = 0.0f, vg = 0.0f, vb = 0.0f;
        tap_rgb(src, r0 + xc0, w00, vr, vg, vb);
        tap_rgb(src, r0 + xc1, w10, vr, vg, vb);
        tap_rgb(src, r1 + xc0, w01, vr, vg, vb);
        tap_rgb(src, r1 + xc1, w11, vr, vg, vb);

        if (p == 0) { vrA = vr; vgA = vg; vbA = vb; }
        else        { vrB = vr; vgB = vg; vbB = vb; }
    }

    size_t base = (size_t)b * CC * HW + rem;
    __stcs(reinterpret_cast<float2*>(out + base),            make_float2(vrA, vrB));
    __stcs(reinterpret_cast<float2*>(out + base + HW),       make_float2(vgA, vgB));
    __stcs(reinterpret_cast<float2*>(out + base + 2 * HW),   make_float2(vbA, vbB));
}

extern "C" void kernel_launch(void* const* d_in, const int* in_sizes, int n_in,
                              void* d_out, int out_size) {
    const float* source_image = (const float*)d_in[0];
    const float* depth_map    = (const float*)d_in[1];
    const float* pose         = (const float*)d_in[2];
    const float* intrinsic    = (const float*)d_in[3];
    float* out = (float*)d_out;

    precompute_mats<<<1, 32>>>(pose, intrinsic);

    const int threads = 256;
    const int pair_threads = BB * HW / 2;
    const int blocks = (pair_threads + threads - 1) / threads;

    pack_hwc_kernel<<<blocks, threads>>>(source_image);
    warp_sample_kernel<<<blocks, threads>>>(depth_map, out);
}

// round 5
// speedup vs baseline: 1.3339x; 1.0284x over previous
#include <cuda_runtime.h>
#include <cuda_fp16.h>
#include <math.h>

#define BB 16
#define CC 3
#define HH 384
#define WW 1280
#define HW (HH * WW)
#define EPSF 1e-7f

// Per-batch fused transform: coord = d * A @ [x,y,1] + tv   (A = K R K^-1, tv = K t)
__device__ float g_A[BB][9];
__device__ float g_tv[BB][3];

// HWC fp16 staging: per pixel 4 halves {R,G,B,pad} = 8 bytes, aligned.
// 62.9 MB static device scratch -> fits in half of L2 (126 MB).
__device__ __half2 g_hwc[(size_t)BB * HW * 2];

__device__ __forceinline__ void compute_mats_one(const float* __restrict__ pose,
                                                 const float* __restrict__ intr,
                                                 int b) {
    float K[9];
#pragma unroll
    for (int i = 0; i < 9; i++) K[i] = intr[b * 9 + i];

    float c00 =  (K[4] * K[8] - K[5] * K[7]);
    float c01 = -(K[3] * K[8] - K[5] * K[6]);
    float c02 =  (K[3] * K[7] - K[4] * K[6]);
    float det = K[0] * c00 + K[1] * c01 + K[2] * c02;
    float id = 1.0f / det;
    float inv[9];
    inv[0] = c00 * id;
    inv[1] = -(K[1] * K[8] - K[2] * K[7]) * id;
    inv[2] =  (K[1] * K[5] - K[2] * K[4]) * id;
    inv[3] = c01 * id;
    inv[4] =  (K[0] * K[8] - K[2] * K[6]) * id;
    inv[5] = -(K[0] * K[5] - K[2] * K[3]) * id;
    inv[6] = c02 * id;
    inv[7] = -(K[0] * K[7] - K[1] * K[6]) * id;
    inv[8] =  (K[0] * K[4] - K[1] * K[3]) * id;

    float ax = pose[b * 6 + 0], ay = pose[b * 6 + 1], az = pose[b * 6 + 2];
    float theta = sqrtf(ax * ax + ay * ay + az * az);
    float ith = 1.0f / (theta + EPSF);
    float x = ax * ith, y = ay * ith, z = az * ith;
    float c = cosf(theta), s = sinf(theta), t = 1.0f - c;
    float R[9];
    R[0] = t * x * x + c;     R[1] = t * x * y - s * z; R[2] = t * z * x + s * y;
    R[3] = t * x * y + s * z; R[4] = t * y * y + c;     R[5] = t * y * z - s * x;
    R[6] = t * z * x - s * y; R[7] = t * y * z + s * x; R[8] = t * z * z + c;

    float KR[9];
#pragma unroll
    for (int i = 0; i < 3; i++)
#pragma unroll
        for (int j = 0; j < 3; j++) {
            float sum = 0.0f;
#pragma unroll
            for (int k = 0; k < 3; k++) sum += K[i * 3 + k] * R[k * 3 + j];
            KR[i * 3 + j] = sum;
        }
#pragma unroll
    for (int i = 0; i < 3; i++)
#pragma unroll
        for (int j = 0; j < 3; j++) {
            float sum = 0.0f;
#pragma unroll
            for (int k = 0; k < 3; k++) sum += KR[i * 3 + k] * inv[k * 3 + j];
            g_A[b][i * 3 + j] = sum;
        }

    float tx = pose[b * 6 + 3], ty = pose[b * 6 + 4], tz = pose[b * 6 + 5];
    g_tv[b][0] = K[0] * tx + K[1] * ty + K[2] * tz;
    g_tv[b][1] = K[3] * tx + K[4] * ty + K[5] * tz;
    g_tv[b][2] = K[6] * tx + K[7] * ty + K[8] * tz;
}

// CHW fp32 -> HWC fp16x4 pack (4 px/thread, float4 I/O) + fused mat precompute.
// Image reads are streaming (.cs); scratch writes default-cached so they stay in L2
// for the sampler's gathers.
__global__ void __launch_bounds__(256)
pack_hwc_kernel(const float* __restrict__ img,
                const float* __restrict__ pose,
                const float* __restrict__ intr) {
    if (blockIdx.x == 0 && threadIdx.x < BB) {
        compute_mats_one(pose, intr, threadIdx.x);
    }

    int tid = blockIdx.x * blockDim.x + threadIdx.x;
    int p = tid * 4;
    if (p >= BB * HW) return;

    int b = p / HW;
    int rem = p - b * HW;
    const float* plane = img + (size_t)b * CC * HW;

    float4 r  = __ldcs(reinterpret_cast<const float4*>(plane + rem));
    float4 g  = __ldcs(reinterpret_cast<const float4*>(plane + HW + rem));
    float4 bl = __ldcs(reinterpret_cast<const float4*>(plane + 2 * HW + rem));

    uint4 pk0, pk1;
    __half2 h;
    h = __floats2half2_rn(r.x, g.x);  pk0.x = *reinterpret_cast<unsigned int*>(&h);
    h = __floats2half2_rn(bl.x, 0.f); pk0.y = *reinterpret_cast<unsigned int*>(&h);
    h = __floats2half2_rn(r.y, g.y);  pk0.z = *reinterpret_cast<unsigned int*>(&h);
    h = __floats2half2_rn(bl.y, 0.f); pk0.w = *reinterpret_cast<unsigned int*>(&h);
    h = __floats2half2_rn(r.z, g.z);  pk1.x = *reinterpret_cast<unsigned int*>(&h);
    h = __floats2half2_rn(bl.z, 0.f); pk1.y = *reinterpret_cast<unsigned int*>(&h);
    h = __floats2half2_rn(r.w, g.w);  pk1.z = *reinterpret_cast<unsigned int*>(&h);
    h = __floats2half2_rn(bl.w, 0.f); pk1.w = *reinterpret_cast<unsigned int*>(&h);

    uint4* dst = reinterpret_cast<uint4*>(&g_hwc[(size_t)p * 2]);
    dst[0] = pk0;   // default caching: keep resident in L2
    dst[1] = pk1;
}

__device__ __forceinline__ void tap_rgb(const uint2* __restrict__ src, int idx,
                                        float wgt, float& vr, float& vg, float& vb) {
    uint2 raw = __ldg(src + idx);
    __half2 rg = *reinterpret_cast<__half2*>(&raw.x);
    __half2 bp = *reinterpret_cast<__half2*>(&raw.y);
    float2 rgf = __half22float2(rg);
    float bf = __low2float(bp);
    vr = fmaf(wgt, rgf.x, vr);
    vg = fmaf(wgt, rgf.y, vg);
    vb = fmaf(wgt, bf, vb);
}

// One thread = 2 horizontally adjacent pixels, HWC fp16 gathers (4 taps/px).
__global__ void __launch_bounds__(256, 4)
warp_sample_kernel(const float* __restrict__ depth,
                   float* __restrict__ out) {
    int tid = blockIdx.x * blockDim.x + threadIdx.x;
    int pix0 = tid * 2;
    if (pix0 >= BB * HW) return;

    int b = pix0 / HW;
    int rem = pix0 - b * HW;          // even; both pixels on the same row
    int h = rem / WW;
    int w = rem - h * WW;

    float a0 = g_A[b][0], a1 = g_A[b][1], a2 = g_A[b][2];
    float a3 = g_A[b][3], a4 = g_A[b][4], a5 = g_A[b][5];
    float a6 = g_A[b][6], a7 = g_A[b][7], a8 = g_A[b][8];
    float t0 = g_tv[b][0], t1 = g_tv[b][1], t2 = g_tv[b][2];

    float2 d2 = __ldcs(reinterpret_cast<const float2*>(depth + pix0));

    float fy = (float)h;
    float rx = a1 * fy + a2;
    float ry = a4 * fy + a5;
    float rz = a7 * fy + a8;

    const uint2* src = reinterpret_cast<const uint2*>(g_hwc) + (size_t)b * HW;

    float vrA = 0.0f, vgA = 0.0f, vbA = 0.0f;
    float vrB = 0.0f, vgB = 0.0f, vbB = 0.0f;

#pragma unroll
    for (int p = 0; p < 2; p++) {
        float fx = (float)(w + p);
        float d  = (p == 0) ? d2.x : d2.y;
        float X = d * (a0 * fx + rx) + t0;
        float Y = d * (a3 * fx + ry) + t1;
        float Z = d * (a6 * fx + rz) + t2 + EPSF;

        float xs = __fdividef(X, Z);
        float ys = __fdividef(Y, Z);

        float x0f = floorf(xs), y0f = floorf(ys);
        float x1f = x0f + 1.0f, y1f = y0f + 1.0f;
        float wx1 = xs - x0f, wx0 = 1.0f - wx1;
        float wy1 = ys - y0f, wy0 = 1.0f - wy1;

        // in-bounds masks on UNCLIPPED coords (reference semantics)
        float ibx0 = (x0f >= 0.0f && x0f <= (float)(WW - 1)) ? 1.0f : 0.0f;
        float ibx1 = (x1f >= 0.0f && x1f <= (float)(WW - 1)) ? 1.0f : 0.0f;
        float iby0 = (y0f >= 0.0f && y0f <= (float)(HH - 1)) ? 1.0f : 0.0f;
        float iby1 = (y1f >= 0.0f && y1f <= (float)(HH - 1)) ? 1.0f : 0.0f;

        int xc0 = (int)fminf(fmaxf(x0f, 0.0f), (float)(WW - 1));
        int xc1 = (int)fminf(fmaxf(x1f, 0.0f), (float)(WW - 1));
        int yc0 = (int)fminf(fmaxf(y0f, 0.0f), (float)(HH - 1));
        int yc1 = (int)fminf(fmaxf(y1f, 0.0f), (float)(HH - 1));

        float w00 = wx0 * wy0 * ibx0 * iby0;
        float w10 = wx1 * wy0 * ibx1 * iby0;
        float w01 = wx0 * wy1 * ibx0 * iby1;
        float w11 = wx1 * wy1 * ibx1 * iby1;

        int r0 = yc0 * WW;
        int r1 = yc1 * WW;

        float vr = 0.0f, vg = 0.0f, vb = 0.0f;
        tap_rgb(src, r0 + xc0, w00, vr, vg, vb);
        tap_rgb(src, r0 + xc1, w10, vr, vg, vb);
        tap_rgb(src, r1 + xc0, w01, vr, vg, vb);
        tap_rgb(src, r1 + xc1, w11, vr, vg, vb);

        if (p == 0) { vrA = vr; vgA = vg; vbA = vb; }
        else        { vrB = vr; vgB = vg; vbB = vb; }
    }

    size_t base = (size_t)b * CC * HW + rem;
    __stcs(reinterpret_cast<float2*>(out + base),            make_float2(vrA, vrB));
    __stcs(reinterpret_cast<float2*>(out + base + HW),       make_float2(vgA, vgB));
    __stcs(reinterpret_cast<float2*>(out + base + 2 * HW),   make_float2(vbA, vbB));
}

extern "C" void kernel_launch(void* const* d_in, const int* in_sizes, int n_in,
                              void* d_out, int out_size) {
    const float* source_image = (const float*)d_in[0];
    const float* depth_map    = (const float*)d_in[1];
    const float* pose         = (const float*)d_in[2];
    const float* intrinsic    = (const float*)d_in[3];
    float* out = (float*)d_out;

    const int threads = 256;

    const int quad_threads = BB * HW / 4;
    pack_hwc_kernel<<<(quad_threads + threads - 1) / threads, threads>>>(
        source_image, pose, intrinsic);

    const int pair_threads = BB * HW / 2;
    warp_sample_kernel<<<(pair_threads + threads - 1) / threads, threads>>>(
        depth_map, out);
}